// round 1
// baseline (speedup 1.0000x reference)
#include <cuda_runtime.h>

#define SCALE_F 0.08838834764831845f

// ---- packed fp32x2 helpers (Blackwell FFMA2 path, PTX-only) ----
static __device__ __forceinline__ void fma2(unsigned long long& d,
                                            unsigned long long a,
                                            unsigned long long b) {
    asm("fma.rn.f32x2 %0, %1, %2, %0;" : "+l"(d) : "l"(a), "l"(b));
}
static __device__ __forceinline__ unsigned long long bcast2(float p) {
    unsigned long long r;
    asm("mov.b64 %0, {%1, %1};" : "=l"(r) : "f"(p));
    return r;
}
static __device__ __forceinline__ float lo32(unsigned long long v) {
    return __uint_as_float((unsigned)v);
}
static __device__ __forceinline__ float hi32(unsigned long long v) {
    return __uint_as_float((unsigned)(v >> 32));
}

// XOR swizzle: storage float-offset of logical 4-float group g of row `row`
// (row stride 128 floats). Chosen so rows spaced by 4 (and by 1) land on
// distinct bank groups for every access pattern in this kernel.
static __device__ __forceinline__ int swz(int row, int g) {
    return row * 128 + ((g ^ ((row >> 2) & 7)) << 2);
}

// smem layout (floats):
//   kbuf   [0,     16384)  K/V chunk: 128 rows x 128, swizzled
//   qbuf   [16384, 20480)  q: 32 rows x 128, swizzled
//   scores [20480, 28672)  scoresT[k][h] : 256 x 32
//   sidx   [28672, 28928)  256 int32 indices
// aliases: redm=kbuf[0..255], reds=kbuf[256..511] (softmax partials),
//          mval=qbuf[0..31], inv=qbuf[32..63] (q is dead by then)
#define SMEM_FLOATS 28928

__global__ void __launch_bounds__(256, 2)
sparse_attn_kernel(const float* __restrict__ q,
                   const float* __restrict__ kv,
                   const float* __restrict__ sink,
                   const int* __restrict__ topk,
                   float* __restrict__ out) {
    extern __shared__ float sm[];
    float* kbuf   = sm;
    float* qbuf   = sm + 16384;
    float* scores = sm + 20480;
    int*   sidx   = (int*)(sm + 28672);
    float* redm = kbuf;
    float* reds = kbuf + 256;
    float* mval = qbuf;
    float* invv = qbuf + 32;

    const int tid = threadIdx.x;
    const int sq  = blockIdx.x;
    const float* qg = q + (long)sq * 4096;

    // ---- load indices + q (swizzled) ----
    sidx[tid] = topk[(long)sq * 256 + tid];
    for (int f = tid; f < 1024; f += 256) {
        int r = f >> 5, g = f & 31;
        float4 v = *(const float4*)(qg + r * 128 + g * 4);
        *(float4*)(qbuf + swz(r, g)) = v;
    }
    __syncthreads();

    const int i  = tid & 7;      // h-block for phases A and C
    const int j  = tid >> 3;     // k-block (A) / d-block (C), 0..31
    const int h0 = i * 4;

    // ================= Phase A: scores = (Q K^T) * SCALE =================
    for (int chunk = 0; chunk < 2; chunk++) {
        if (chunk) __syncthreads();
        // gather K chunk (128 rows x 512B, coalesced, swizzled store)
        for (int f = tid; f < 4096; f += 256) {
            int r = f >> 5, g = f & 31;
            long id = sidx[chunk * 128 + r];
            float4 v = *(const float4*)(kv + id * 256 + g * 4);
            *(float4*)(kbuf + swz(r, g)) = v;
        }
        __syncthreads();

        const int k0 = j * 4;
        unsigned long long acc[16];
#pragma unroll
        for (int t = 0; t < 16; t++) acc[t] = 0ULL;

#pragma unroll 4
        for (int s = 0; s < 32; s++) {
            ulonglong2 qa[4], ka[4];
#pragma unroll
            for (int a = 0; a < 4; a++)
                qa[a] = *(const ulonglong2*)(qbuf + swz(h0 + a, s));
#pragma unroll
            for (int c = 0; c < 4; c++)
                ka[c] = *(const ulonglong2*)(kbuf + swz(k0 + c, s));
#pragma unroll
            for (int a = 0; a < 4; a++)
#pragma unroll
                for (int c = 0; c < 4; c++) {
                    fma2(acc[a * 4 + c], qa[a].x, ka[c].x);
                    fma2(acc[a * 4 + c], qa[a].y, ka[c].y);
                }
        }
#pragma unroll
        for (int a = 0; a < 4; a++)
#pragma unroll
            for (int c = 0; c < 4; c++) {
                unsigned long long v = acc[a * 4 + c];
                float sc = (lo32(v) + hi32(v)) * SCALE_F;
                scores[(chunk * 128 + k0 + c) * 32 + h0 + a] = sc;
            }
    }
    __syncthreads();   // Phase A done; kbuf reusable as reduction scratch

    // ================= Phase B: sink softmax (normalize deferred) ========
    {
        const int h = tid & 31, sl = tid >> 5;   // 8 slices x 32 k
        float mx = -1e30f;
#pragma unroll 4
        for (int kk = sl * 32; kk < sl * 32 + 32; kk++)
            mx = fmaxf(mx, scores[kk * 32 + h]);
        redm[sl * 32 + h] = mx;
        __syncthreads();
        if (tid < 32) {
            float m = sink[tid];
#pragma unroll
            for (int s = 0; s < 8; s++) m = fmaxf(m, redm[s * 32 + tid]);
            mval[tid] = m;
        }
        __syncthreads();
        const float m = mval[h];
        float ssum = 0.f;
#pragma unroll 4
        for (int kk = sl * 32; kk < sl * 32 + 32; kk++) {
            float e = __expf(scores[kk * 32 + h] - m);
            scores[kk * 32 + h] = e;
            ssum += e;
        }
        reds[sl * 32 + h] = ssum;
        __syncthreads();
        if (tid < 32) {
            float den = __expf(sink[tid] - mval[tid]);
#pragma unroll
            for (int s = 0; s < 8; s++) den += reds[s * 32 + tid];
            invv[tid] = 1.0f / den;
        }
        // next __syncthreads (top of Phase C) orders invv/reds vs kbuf reuse
    }

    // ================= Phase C: out = (E V) * inv ========================
    const int d0 = j * 4;
    unsigned long long oacc[8];
#pragma unroll
    for (int t = 0; t < 8; t++) oacc[t] = 0ULL;

    for (int chunk = 0; chunk < 2; chunk++) {
        __syncthreads();   // previous kbuf consumers (red scratch / chunk) done
        for (int f = tid; f < 4096; f += 256) {
            int r = f >> 5, g = f & 31;
            long id = sidx[chunk * 128 + r];
            float4 v = *(const float4*)(kv + id * 256 + 128 + g * 4);
            *(float4*)(kbuf + swz(r, g)) = v;
        }
        __syncthreads();

#pragma unroll 4
        for (int kk = 0; kk < 128; kk++) {
            const float4 p = *(const float4*)(scores + (chunk * 128 + kk) * 32 + h0);
            const ulonglong2 vv = *(const ulonglong2*)(kbuf + swz(kk, j));
            unsigned long long p0 = bcast2(p.x), p1 = bcast2(p.y);
            unsigned long long p2 = bcast2(p.z), p3 = bcast2(p.w);
            fma2(oacc[0], p0, vv.x); fma2(oacc[1], p0, vv.y);
            fma2(oacc[2], p1, vv.x); fma2(oacc[3], p1, vv.y);
            fma2(oacc[4], p2, vv.x); fma2(oacc[5], p2, vv.y);
            fma2(oacc[6], p3, vv.x); fma2(oacc[7], p3, vv.y);
        }
    }

    // ---- epilogue: apply 1/denom, store coalesced float4 per head-row ----
#pragma unroll
    for (int a = 0; a < 4; a++) {
        float iv = invv[h0 + a];
        float4 o;
        o.x = lo32(oacc[a * 2]) * iv;
        o.y = hi32(oacc[a * 2]) * iv;
        o.z = lo32(oacc[a * 2 + 1]) * iv;
        o.w = hi32(oacc[a * 2 + 1]) * iv;
        *(float4*)(out + (long)sq * 4096 + (h0 + a) * 128 + d0) = o;
    }
}

extern "C" void kernel_launch(void* const* d_in, const int* in_sizes, int n_in,
                              void* d_out, int out_size) {
    const float* q    = (const float*)d_in[0];
    const float* kv   = (const float*)d_in[1];
    const float* sink = (const float*)d_in[2];
    const int*   topk = (const int*)d_in[3];
    float* out = (float*)d_out;

    const int smem_bytes = SMEM_FLOATS * 4;   // 115,712 B
    cudaFuncSetAttribute(sparse_attn_kernel,
                         cudaFuncAttributeMaxDynamicSharedMemorySize, smem_bytes);
    sparse_attn_kernel<<<2048, 256, smem_bytes>>>(q, kv, sink, topk, out);
}

// round 2
// speedup vs baseline: 1.0512x; 1.0512x over previous
#include <cuda_runtime.h>

#define SCALE_F 0.08838834764831845f

// ---- packed fp32x2 helpers (Blackwell FFMA2 path, PTX-only) ----
static __device__ __forceinline__ void fma2(unsigned long long& d,
                                            unsigned long long a,
                                            unsigned long long b) {
    asm("fma.rn.f32x2 %0, %1, %2, %0;" : "+l"(d) : "l"(a), "l"(b));
}
static __device__ __forceinline__ unsigned long long bcast2(float p) {
    unsigned long long r;
    asm("mov.b64 %0, {%1, %1};" : "=l"(r) : "f"(p));
    return r;
}
static __device__ __forceinline__ float lo32(unsigned long long v) {
    return __uint_as_float((unsigned)v);
}
static __device__ __forceinline__ float hi32(unsigned long long v) {
    return __uint_as_float((unsigned)(v >> 32));
}

// XOR swizzle: storage float-offset of logical 4-float group g of row `row`
// (row stride 128 floats). Chosen so rows spaced by 4 (and by 1) land on
// distinct bank groups for every access pattern in this kernel.
static __device__ __forceinline__ int swz(int row, int g) {
    return row * 128 + ((g ^ ((row >> 2) & 7)) << 2);
}

// smem layout (floats):
//   kbuf   [0,     16384)  K/V chunk: 128 rows x 128, swizzled
//   qbuf   [16384, 20480)  q: 32 rows x 128, swizzled
//   scores [20480, 28672)  scoresT[k][h] : 256 x 32
//   sidx   [28672, 28928)  256 int32 indices
// aliases: redm=kbuf[0..255], reds=kbuf[256..511] (softmax partials),
//          mval=qbuf[0..31], inv=qbuf[32..63] (q is dead by then)
#define SMEM_FLOATS 28928

__global__ void __launch_bounds__(256, 2)
sparse_attn_kernel(const float* __restrict__ q,
                   const float* __restrict__ kv,
                   const float* __restrict__ sink,
                   const int* __restrict__ topk,
                   float* __restrict__ out) {
    extern __shared__ float sm[];
    float* kbuf   = sm;
    float* qbuf   = sm + 16384;
    float* scores = sm + 20480;
    int*   sidx   = (int*)(sm + 28672);
    float* redm = kbuf;
    float* reds = kbuf + 256;
    float* mval = qbuf;
    float* invv = qbuf + 32;

    const int tid = threadIdx.x;
    const int sq  = blockIdx.x;
    const float* qg = q + (long)sq * 4096;

    // ---- load indices + q (swizzled) ----
    sidx[tid] = topk[(long)sq * 256 + tid];
    for (int f = tid; f < 1024; f += 256) {
        int r = f >> 5, g = f & 31;
        float4 v = *(const float4*)(qg + r * 128 + g * 4);
        *(float4*)(qbuf + swz(r, g)) = v;
    }
    __syncthreads();

    const int i  = tid & 7;      // h-block for phases A and C
    const int j  = tid >> 3;     // k-block (A) / d-block (C), 0..31
    const int h0 = i * 4;

    // ================= Phase A: scores = (Q K^T) * SCALE =================
    for (int chunk = 0; chunk < 2; chunk++) {
        if (chunk) __syncthreads();
        // gather K chunk (128 rows x 512B, coalesced, swizzled store)
        for (int f = tid; f < 4096; f += 256) {
            int r = f >> 5, g = f & 31;
            long id = sidx[chunk * 128 + r];
            float4 v = *(const float4*)(kv + id * 256 + g * 4);
            *(float4*)(kbuf + swz(r, g)) = v;
        }
        __syncthreads();

        const int k0 = j * 4;
        unsigned long long acc[16];
#pragma unroll
        for (int t = 0; t < 16; t++) acc[t] = 0ULL;

#pragma unroll 4
        for (int s = 0; s < 32; s++) {
            ulonglong2 qa[4], ka[4];
#pragma unroll
            for (int a = 0; a < 4; a++)
                qa[a] = *(const ulonglong2*)(qbuf + swz(h0 + a, s));
#pragma unroll
            for (int c = 0; c < 4; c++)
                ka[c] = *(const ulonglong2*)(kbuf + swz(k0 + c, s));
#pragma unroll
            for (int a = 0; a < 4; a++)
#pragma unroll
                for (int c = 0; c < 4; c++) {
                    fma2(acc[a * 4 + c], qa[a].x, ka[c].x);
                    fma2(acc[a * 4 + c], qa[a].y, ka[c].y);
                }
        }
#pragma unroll
        for (int a = 0; a < 4; a++)
#pragma unroll
            for (int c = 0; c < 4; c++) {
                unsigned long long v = acc[a * 4 + c];
                float sc = (lo32(v) + hi32(v)) * SCALE_F;
                scores[(chunk * 128 + k0 + c) * 32 + h0 + a] = sc;
            }
    }
    __syncthreads();   // Phase A done; kbuf reusable as reduction scratch

    // ================= Phase B: sink softmax (normalize deferred) ========
    {
        const int h = tid & 31, sl = tid >> 5;   // 8 slices x 32 k
        float mx = -1e30f;
#pragma unroll 4
        for (int kk = sl * 32; kk < sl * 32 + 32; kk++)
            mx = fmaxf(mx, scores[kk * 32 + h]);
        redm[sl * 32 + h] = mx;
        __syncthreads();
        if (tid < 32) {
            float m = sink[tid];
#pragma unroll
            for (int s = 0; s < 8; s++) m = fmaxf(m, redm[s * 32 + tid]);
            mval[tid] = m;
        }
        __syncthreads();
        const float m = mval[h];
        float ssum = 0.f;
#pragma unroll 4
        for (int kk = sl * 32; kk < sl * 32 + 32; kk++) {
            float e = __expf(scores[kk * 32 + h] - m);
            scores[kk * 32 + h] = e;
            ssum += e;
        }
        reds[sl * 32 + h] = ssum;
        __syncthreads();
        if (tid < 32) {
            float den = __expf(sink[tid] - mval[tid]);
#pragma unroll
            for (int s = 0; s < 8; s++) den += reds[s * 32 + tid];
            invv[tid] = 1.0f / den;
        }
        // next __syncthreads (top of Phase C) orders invv/reds vs kbuf reuse
    }

    // ================= Phase C: out = (E V) * inv ========================
    const int d0 = j * 4;
    unsigned long long oacc[8];
#pragma unroll
    for (int t = 0; t < 8; t++) oacc[t] = 0ULL;

    for (int chunk = 0; chunk < 2; chunk++) {
        __syncthreads();   // previous kbuf consumers (red scratch / chunk) done
        for (int f = tid; f < 4096; f += 256) {
            int r = f >> 5, g = f & 31;
            long id = sidx[chunk * 128 + r];
            float4 v = *(const float4*)(kv + id * 256 + 128 + g * 4);
            *(float4*)(kbuf + swz(r, g)) = v;
        }
        __syncthreads();

#pragma unroll 4
        for (int kk = 0; kk < 128; kk++) {
            const float4 p = *(const float4*)(scores + (chunk * 128 + kk) * 32 + h0);
            const ulonglong2 vv = *(const ulonglong2*)(kbuf + swz(kk, j));
            unsigned long long p0 = bcast2(p.x), p1 = bcast2(p.y);
            unsigned long long p2 = bcast2(p.z), p3 = bcast2(p.w);
            fma2(oacc[0], p0, vv.x); fma2(oacc[1], p0, vv.y);
            fma2(oacc[2], p1, vv.x); fma2(oacc[3], p1, vv.y);
            fma2(oacc[4], p2, vv.x); fma2(oacc[5], p2, vv.y);
            fma2(oacc[6], p3, vv.x); fma2(oacc[7], p3, vv.y);
        }
    }

    // ---- epilogue: apply 1/denom, store coalesced float4 per head-row ----
#pragma unroll
    for (int a = 0; a < 4; a++) {
        float iv = invv[h0 + a];
        float4 o;
        o.x = lo32(oacc[a * 2]) * iv;
        o.y = hi32(oacc[a * 2]) * iv;
        o.z = lo32(oacc[a * 2 + 1]) * iv;
        o.w = hi32(oacc[a * 2 + 1]) * iv;
        *(float4*)(out + (long)sq * 4096 + (h0 + a) * 128 + d0) = o;
    }
}

extern "C" void kernel_launch(void* const* d_in, const int* in_sizes, int n_in,
                              void* d_out, int out_size) {
    const float* q    = (const float*)d_in[0];
    const float* kv   = (const float*)d_in[1];
    const float* sink = (const float*)d_in[2];
    const int*   topk = (const int*)d_in[3];
    float* out = (float*)d_out;

    const int smem_bytes = SMEM_FLOATS * 4;   // 115,712 B
    cudaFuncSetAttribute(sparse_attn_kernel,
                         cudaFuncAttributeMaxDynamicSharedMemorySize, smem_bytes);
    sparse_attn_kernel<<<2048, 256, smem_bytes>>>(q, kv, sink, topk, out);
}

// round 4
// speedup vs baseline: 1.7160x; 1.6324x over previous
#include <cuda_runtime.h>
#include <cstdint>

#define SCALE_F 0.08838834764831845f

// ---------------- smem byte offsets ----------------
// KT_H/KT_L: K or V chunk tile, 128 rows x 128 bf16 (256B/row), swizzled.
// QT_H/QT_L: Q tile 32 x 128. After Phase A, QT region (16KB) becomes P_L.
// P_H: P tile 32 h x 256 k bf16 (512B/row).
// scoresT aliases KT region: 256 x 34 f32 (stride 34 -> float2-aligned pairs).
#define KT_H   0
#define KT_L   32768
#define QT_H   65536
#define QT_L   73728
#define P_LO   65536     // aliases QT_H..QT_L (Q dead by Phase B)
#define P_HI   81920
#define REDM   98304
#define REDS   99328
#define MVAL   100352
#define INVV   100480
#define SIDX   100608
#define SMEM_BYTES 101632

// ---------------- helpers ----------------
static __device__ __forceinline__ uint32_t smem_u32(const void* p) {
    uint32_t a;
    asm("{ .reg .u64 t; cvta.to.shared.u64 t, %1; cvt.u32.u64 %0, t; }" : "=r"(a) : "l"(p));
    return a;
}
static __device__ __forceinline__ void ldm4(uint32_t* r, uint32_t addr) {
    asm volatile("ldmatrix.sync.aligned.m8n8.x4.shared.b16 {%0,%1,%2,%3}, [%4];"
                 : "=r"(r[0]), "=r"(r[1]), "=r"(r[2]), "=r"(r[3]) : "r"(addr));
}
static __device__ __forceinline__ void ldm4t(uint32_t* r, uint32_t addr) {
    asm volatile("ldmatrix.sync.aligned.m8n8.x4.trans.shared.b16 {%0,%1,%2,%3}, [%4];"
                 : "=r"(r[0]), "=r"(r[1]), "=r"(r[2]), "=r"(r[3]) : "r"(addr));
}
static __device__ __forceinline__ void mma16816(float* c, const uint32_t* a,
                                                uint32_t b0, uint32_t b1) {
    asm volatile("mma.sync.aligned.m16n8k16.row.col.f32.bf16.bf16.f32 "
                 "{%0,%1,%2,%3}, {%4,%5,%6,%7}, {%8,%9}, {%0,%1,%2,%3};"
                 : "+f"(c[0]), "+f"(c[1]), "+f"(c[2]), "+f"(c[3])
                 : "r"(a[0]), "r"(a[1]), "r"(a[2]), "r"(a[3]), "r"(b0), "r"(b1));
}
// split fp32 -> (hi bf16, lo bf16)
static __device__ __forceinline__ void sp(float x, unsigned short& h, unsigned short& l) {
    asm("cvt.rn.bf16.f32 %0, %1;" : "=h"(h) : "f"(x));
    float r = x - __uint_as_float(((unsigned)h) << 16);
    asm("cvt.rn.bf16.f32 %0, %1;" : "=h"(l) : "f"(r));
}
// convert 8 floats -> packed hi uint4 + lo uint4
static __device__ __forceinline__ void cv8(const float* f, uint4& H, uint4& L) {
    unsigned short h[8], l[8];
#pragma unroll
    for (int i = 0; i < 8; i++) sp(f[i], h[i], l[i]);
    H.x = h[0] | ((unsigned)h[1] << 16); H.y = h[2] | ((unsigned)h[3] << 16);
    H.z = h[4] | ((unsigned)h[5] << 16); H.w = h[6] | ((unsigned)h[7] << 16);
    L.x = l[0] | ((unsigned)l[1] << 16); L.y = l[2] | ((unsigned)l[3] << 16);
    L.z = l[4] | ((unsigned)l[5] << 16); L.w = l[6] | ((unsigned)l[7] << 16);
}

__global__ void __launch_bounds__(256, 2)
sparse_attn_hmma(const float* __restrict__ q, const float* __restrict__ kv,
                 const float* __restrict__ sink, const int* __restrict__ topk,
                 float* __restrict__ out) {
    extern __shared__ __align__(1024) unsigned char smem[];
    const uint32_t sb = smem_u32(smem);
    const int tid = threadIdx.x, wid = tid >> 5, lid = tid & 31;
    const int l15 = lid & 15, lh = lid >> 4;
    const int sq = blockIdx.x;
    float* scoresT = (float*)smem;          // [256][34] f32, aliases KT
    int*   sidx    = (int*)(smem + SIDX);
    float* redm = (float*)(smem + REDM);
    float* reds = (float*)(smem + REDS);
    float* mval = (float*)(smem + MVAL);
    float* invv = (float*)(smem + INVV);

    sidx[tid] = topk[(long)sq * 256 + tid];

    // ---- Q convert: scale + split (32 rows x 16 chunks of 16B) ----
    const float* qg = q + (long)sq * 4096;
    for (int f = tid; f < 512; f += 256) {
        int r = f >> 4, ch = f & 15;
        float v[8];
        *(float4*)(v) = *(const float4*)(qg + r * 128 + ch * 8);
        *(float4*)(v + 4) = *(const float4*)(qg + r * 128 + ch * 8 + 4);
#pragma unroll
        for (int i = 0; i < 8; i++) v[i] *= SCALE_F;
        uint4 H, L; cv8(v, H, L);
        uint32_t o = r * 256 + (((ch) ^ (r & 7)) << 4);
        *(uint4*)(smem + QT_H + o) = H;
        *(uint4*)(smem + QT_L + o) = L;
    }
    __syncthreads();

    // ================= Phase A: scores = K_g . Q^T ====================
    float sc[32];
#pragma unroll
    for (int t = 0; t < 32; t++) sc[t] = 0.f;
    const int karow = wid * 16 + l15;
    const int qrow0 = l15, qrow1 = 16 + l15;

    for (int c = 0; c < 2; c++) {
        if (c) __syncthreads();
        for (int f = tid; f < 2048; f += 256) {
            int r = f >> 4, ch = f & 15;
            long id = sidx[c * 128 + r];
            float v[8];
            *(float4*)(v) = *(const float4*)(kv + id * 256 + ch * 8);
            *(float4*)(v + 4) = *(const float4*)(kv + id * 256 + ch * 8 + 4);
            uint4 H, L; cv8(v, H, L);
            uint32_t o = r * 256 + (((ch) ^ (r & 7)) << 4);
            *(uint4*)(smem + KT_H + o) = H;
            *(uint4*)(smem + KT_L + o) = L;
        }
        __syncthreads();

        float* scc = sc + c * 16;
#pragma unroll
        for (int s = 0; s < 8; s++) {
            int chsel = 2 * s + lh;
            uint32_t ao = karow * 256 + ((chsel ^ (karow & 7)) << 4);
            uint32_t q0 = qrow0 * 256 + ((chsel ^ (qrow0 & 7)) << 4);
            uint32_t q1 = qrow1 * 256 + ((chsel ^ (qrow1 & 7)) << 4);
            uint32_t aH[4], aL[4], bH0[4], bH1[4], bL0[4], bL1[4];
            ldm4(aH, sb + KT_H + ao);
            ldm4(aL, sb + KT_L + ao);
            ldm4(bH0, sb + QT_H + q0);
            ldm4(bH1, sb + QT_H + q1);
            ldm4(bL0, sb + QT_L + q0);
            ldm4(bL1, sb + QT_L + q1);
            // hh
            mma16816(scc + 0,  aH, bH0[0], bH0[2]);
            mma16816(scc + 4,  aH, bH0[1], bH0[3]);
            mma16816(scc + 8,  aH, bH1[0], bH1[2]);
            mma16816(scc + 12, aH, bH1[1], bH1[3]);
            // hl
            mma16816(scc + 0,  aH, bL0[0], bL0[2]);
            mma16816(scc + 4,  aH, bL0[1], bL0[3]);
            mma16816(scc + 8,  aH, bL1[0], bL1[2]);
            mma16816(scc + 12, aH, bL1[1], bL1[3]);
            // lh
            mma16816(scc + 0,  aL, bH0[0], bH0[2]);
            mma16816(scc + 4,  aL, bH0[1], bH0[3]);
            mma16816(scc + 8,  aL, bH1[0], bH1[2]);
            mma16816(scc + 12, aL, bH1[1], bH1[3]);
        }
    }
    __syncthreads();   // KT dead -> scoresT

    // ---- dump scores to smem (stride 34, float2 pairs) ----
#pragma unroll
    for (int c = 0; c < 2; c++)
#pragma unroll
        for (int j = 0; j < 4; j++) {
            int k = c * 128 + wid * 16 + (lid >> 2);
            int h = j * 8 + (lid & 3) * 2;
            *(float2*)(scoresT + k * 34 + h) =
                make_float2(sc[c * 16 + j * 4 + 0], sc[c * 16 + j * 4 + 1]);
            *(float2*)(scoresT + (k + 8) * 34 + h) =
                make_float2(sc[c * 16 + j * 4 + 2], sc[c * 16 + j * 4 + 3]);
        }
    __syncthreads();

    // ================= Phase B: sink softmax -> split P ===============
    {
        const int h = tid & 31, sl = tid >> 5;
        float mx = -1e30f;
#pragma unroll 4
        for (int k = sl * 32; k < sl * 32 + 32; k++)
            mx = fmaxf(mx, scoresT[k * 34 + h]);
        redm[sl * 32 + h] = mx;
        __syncthreads();
        if (tid < 32) {
            float m = sink[tid];
#pragma unroll
            for (int s = 0; s < 8; s++) m = fmaxf(m, redm[s * 32 + tid]);
            mval[tid] = m;
        }
        __syncthreads();
        const float m = mval[h];
        float ssum = 0.f;
#pragma unroll 2
        for (int kp = 0; kp < 16; kp++) {
            int k = sl * 32 + kp * 2;
            float e0 = __expf(scoresT[k * 34 + h] - m);
            float e1 = __expf(scoresT[(k + 1) * 34 + h] - m);
            ssum += e0 + e1;
            unsigned short h0, l0, h1, l1;
            sp(e0, h0, l0); sp(e1, h1, l1);
            uint32_t o = h * 512 + ((((k >> 3)) ^ (h & 7)) << 4) + ((k & 7) << 1);
            *(unsigned*)(smem + P_HI + o) = h0 | ((unsigned)h1 << 16);
            *(unsigned*)(smem + P_LO + o) = l0 | ((unsigned)l1 << 16);
        }
        reds[sl * 32 + h] = ssum;
        __syncthreads();
        if (tid < 32) {
            float den = __expf(sink[tid] - mval[tid]);
#pragma unroll
            for (int s = 0; s < 8; s++) den += reds[s * 32 + tid];
            invv[tid] = 1.f / den;
        }
    }

    // ================= Phase C: out = P . V ===========================
    float oacc[16];
#pragma unroll
    for (int t = 0; t < 16; t++) oacc[t] = 0.f;
    const int prow = (wid & 1) * 16 + l15;
    const uint32_t vc0 = (wid >> 1) * 4 + lh;   // V chunk base (d-block 0)

    for (int c = 0; c < 2; c++) {
        __syncthreads();   // prior KT readers done (scoresT / chunk0 mma)
        for (int f = tid; f < 2048; f += 256) {
            int r = f >> 4, ch = f & 15;
            long id = sidx[c * 128 + r];
            float v[8];
            *(float4*)(v) = *(const float4*)(kv + id * 256 + 128 + ch * 8);
            *(float4*)(v + 4) = *(const float4*)(kv + id * 256 + 128 + ch * 8 + 4);
            uint4 H, L; cv8(v, H, L);
            uint32_t o = r * 256 + (((ch) ^ (r & 7)) << 4);
            *(uint4*)(smem + KT_H + o) = H;
            *(uint4*)(smem + KT_L + o) = L;
        }
        __syncthreads();

#pragma unroll
        for (int s = 0; s < 8; s++) {
            int pch = c * 16 + 2 * s + lh;
            uint32_t po = prow * 512 + ((pch ^ (prow & 7)) << 4);
            uint32_t vrow = s * 16 + l15;
            uint32_t v0 = vrow * 256 + (((vc0) ^ (vrow & 7)) << 4);
            uint32_t v1 = vrow * 256 + (((vc0 + 2) ^ (vrow & 7)) << 4);
            uint32_t aH[4], aL[4], vH0[4], vH1[4], vL0[4], vL1[4];
            ldm4(aH, sb + P_HI + po);
            ldm4(aL, sb + P_LO + po);
            ldm4t(vH0, sb + KT_H + v0);
            ldm4t(vH1, sb + KT_H + v1);
            ldm4t(vL0, sb + KT_L + v0);
            ldm4t(vL1, sb + KT_L + v1);
            // hh
            mma16816(oacc + 0,  aH, vH0[0], vH0[1]);
            mma16816(oacc + 4,  aH, vH0[2], vH0[3]);
            mma16816(oacc + 8,  aH, vH1[0], vH1[1]);
            mma16816(oacc + 12, aH, vH1[2], vH1[3]);
            // hl
            mma16816(oacc + 0,  aH, vL0[0], vL0[1]);
            mma16816(oacc + 4,  aH, vL0[2], vL0[3]);
            mma16816(oacc + 8,  aH, vL1[0], vL1[1]);
            mma16816(oacc + 12, aH, vL1[2], vL1[3]);
            // lh
            mma16816(oacc + 0,  aL, vH0[0], vH0[1]);
            mma16816(oacc + 4,  aL, vH0[2], vH0[3]);
            mma16816(oacc + 8,  aL, vH1[0], vH1[1]);
            mma16816(oacc + 12, aL, vH1[2], vH1[3]);
        }
    }

    // ---- epilogue: normalize + store ----
    {
        const int h0 = (wid & 1) * 16 + (lid >> 2);
        const int d0 = (wid >> 1) * 32 + (lid & 3) * 2;
        const float i0 = invv[h0], i1 = invv[h0 + 8];
        float* op = out + (long)sq * 4096;
#pragma unroll
        for (int j = 0; j < 4; j++) {
            int d = d0 + j * 8;
            *(float2*)(op + h0 * 128 + d) =
                make_float2(oacc[j * 4 + 0] * i0, oacc[j * 4 + 1] * i0);
            *(float2*)(op + (h0 + 8) * 128 + d) =
                make_float2(oacc[j * 4 + 2] * i1, oacc[j * 4 + 3] * i1);
        }
    }
}

extern "C" void kernel_launch(void* const* d_in, const int* in_sizes, int n_in,
                              void* d_out, int out_size) {
    (void)in_sizes; (void)n_in; (void)out_size;
    const float* q    = (const float*)d_in[0];
    const float* kv   = (const float*)d_in[1];
    const float* sink = (const float*)d_in[2];
    const int*   topk = (const int*)d_in[3];
    float* out = (float*)d_out;

    cudaFuncSetAttribute(sparse_attn_hmma,
                         cudaFuncAttributeMaxDynamicSharedMemorySize, SMEM_BYTES);
    sparse_attn_hmma<<<2048, 256, SMEM_BYTES>>>(q, kv, sink, topk, out);
}

// round 5
// speedup vs baseline: 2.1370x; 1.2453x over previous
#include <cuda_runtime.h>
#include <cstdint>

#define SCALE_F 0.08838834764831845f

// ---------------- smem byte offsets ----------------
// KB(b): half-chunk K/V tile, 64 rows x 128 bf16 (256B/row), hi+lo, double buffered
#define KBH(b) ((b) * 32768)
#define KBL(b) ((b) * 32768 + 16384)
#define QT_H   65536     // Q hi: 32 rows x 256B
#define QT_L   73728     // Q lo
#define P_LO   65536     // P lo: 32 h x 512B  (aliases QT: Q dead by softmax)
#define P_HI   81920     // P hi: 32 h x 512B
#define REDM   98304     // 4 warps x 32 f32
#define REDS   98816
#define INVV   99328     // 32 f32
#define SMEM_BYTES 99456

// ---------------- helpers ----------------
static __device__ __forceinline__ uint32_t smem_u32(const void* p) {
    uint32_t a;
    asm("{ .reg .u64 t; cvta.to.shared.u64 t, %1; cvt.u32.u64 %0, t; }" : "=r"(a) : "l"(p));
    return a;
}
static __device__ __forceinline__ void ldm4(uint32_t* r, uint32_t addr) {
    asm volatile("ldmatrix.sync.aligned.m8n8.x4.shared.b16 {%0,%1,%2,%3}, [%4];"
                 : "=r"(r[0]), "=r"(r[1]), "=r"(r[2]), "=r"(r[3]) : "r"(addr));
}
static __device__ __forceinline__ void ldm4t(uint32_t* r, uint32_t addr) {
    asm volatile("ldmatrix.sync.aligned.m8n8.x4.trans.shared.b16 {%0,%1,%2,%3}, [%4];"
                 : "=r"(r[0]), "=r"(r[1]), "=r"(r[2]), "=r"(r[3]) : "r"(addr));
}
static __device__ __forceinline__ void mma16816(float* c, const uint32_t* a,
                                                uint32_t b0, uint32_t b1) {
    asm volatile("mma.sync.aligned.m16n8k16.row.col.f32.bf16.bf16.f32 "
                 "{%0,%1,%2,%3}, {%4,%5,%6,%7}, {%8,%9}, {%0,%1,%2,%3};"
                 : "+f"(c[0]), "+f"(c[1]), "+f"(c[2]), "+f"(c[3])
                 : "r"(a[0]), "r"(a[1]), "r"(a[2]), "r"(a[3]), "r"(b0), "r"(b1));
}
static __device__ __forceinline__ void sp(float x, unsigned short& h, unsigned short& l) {
    asm("cvt.rn.bf16.f32 %0, %1;" : "=h"(h) : "f"(x));
    float r = x - __uint_as_float(((unsigned)h) << 16);
    asm("cvt.rn.bf16.f32 %0, %1;" : "=h"(l) : "f"(r));
}
static __device__ __forceinline__ void cv8(const float* f, uint4& H, uint4& L) {
    unsigned short h[8], l[8];
#pragma unroll
    for (int i = 0; i < 8; i++) sp(f[i], h[i], l[i]);
    H.x = h[0] | ((unsigned)h[1] << 16); H.y = h[2] | ((unsigned)h[3] << 16);
    H.z = h[4] | ((unsigned)h[5] << 16); H.w = h[6] | ((unsigned)h[7] << 16);
    L.x = l[0] | ((unsigned)l[1] << 16); L.y = l[2] | ((unsigned)l[3] << 16);
    L.z = l[4] | ((unsigned)l[5] << 16); L.w = l[6] | ((unsigned)l[7] << 16);
}

// producer: gather + split-convert one 64-row half into buffer buf
static __device__ __forceinline__ void prod_half(
    unsigned char* smem, const float* kv, const int* topk,
    int sq, int base, int hc, int buf, int pt) {
#pragma unroll
    for (int it = 0; it < 8; it++) {
        int f = pt + it * 128;
        int r = f >> 4, ch = f & 15;
        int id = __ldg(topk + sq * 256 + hc * 64 + r);
        const float* src = kv + (long)id * 256 + base + ch * 8;
        float v[8];
        *(float4*)(v) = *(const float4*)(src);
        *(float4*)(v + 4) = *(const float4*)(src + 4);
        uint4 H, L; cv8(v, H, L);
        uint32_t o = r * 256 + ((ch ^ (r & 7)) << 4);
        *(uint4*)(smem + KBH(buf) + o) = H;
        *(uint4*)(smem + KBL(buf) + o) = L;
    }
}

// consumer Phase A: 64-row half-chunk, warp tile M16 x N32, 3-term split
static __device__ __forceinline__ void mma_A(
    uint32_t sb, int buf, float* scc, int cw, int l15, int lh) {
    const int arow = cw * 16 + l15;
    const int qrow0 = l15, qrow1 = 16 + l15;
#pragma unroll
    for (int s = 0; s < 8; s++) {
        int ch = 2 * s + lh;
        uint32_t ao = arow * 256 + ((ch ^ (arow & 7)) << 4);
        uint32_t q0 = qrow0 * 256 + ((ch ^ (qrow0 & 7)) << 4);
        uint32_t q1 = qrow1 * 256 + ((ch ^ (qrow1 & 7)) << 4);
        uint32_t aH[4], aL[4], bH0[4], bH1[4], bL0[4], bL1[4];
        ldm4(aH, sb + KBH(buf) + ao);
        ldm4(aL, sb + KBL(buf) + ao);
        ldm4(bH0, sb + QT_H + q0);
        ldm4(bH1, sb + QT_H + q1);
        ldm4(bL0, sb + QT_L + q0);
        ldm4(bL1, sb + QT_L + q1);
        // hh
        mma16816(scc + 0,  aH, bH0[0], bH0[2]);
        mma16816(scc + 4,  aH, bH0[1], bH0[3]);
        mma16816(scc + 8,  aH, bH1[0], bH1[2]);
        mma16816(scc + 12, aH, bH1[1], bH1[3]);
        // hl
        mma16816(scc + 0,  aH, bL0[0], bL0[2]);
        mma16816(scc + 4,  aH, bL0[1], bL0[3]);
        mma16816(scc + 8,  aH, bL1[0], bL1[2]);
        mma16816(scc + 12, aH, bL1[1], bL1[3]);
        // lh
        mma16816(scc + 0,  aL, bH0[0], bH0[2]);
        mma16816(scc + 4,  aL, bH0[1], bH0[3]);
        mma16816(scc + 8,  aL, bH1[0], bH1[2]);
        mma16816(scc + 12, aL, bH1[1], bH1[3]);
    }
}

// consumer Phase C: 64 V-rows in buf (global k half hcl), warp tile M32h x N32d
static __device__ __forceinline__ void mma_C(
    uint32_t sb, int buf, int hcl, float* oacc, int cw, int l15, int lh) {
#pragma unroll
    for (int s = 0; s < 4; s++) {
        int pch = hcl * 8 + 2 * s + lh;
        uint32_t po0 = l15 * 512 + ((pch ^ (l15 & 7)) << 4);
        uint32_t po1 = po0 + 8192;   // (16+l15)&7 == l15&7
        uint32_t aH0[4], aH1[4], aL0[4], aL1[4];
        ldm4(aH0, sb + P_HI + po0);
        ldm4(aH1, sb + P_HI + po1);
        ldm4(aL0, sb + P_LO + po0);
        ldm4(aL1, sb + P_LO + po1);
        int vrow = s * 16 + l15;
        uint32_t vc0 = cw * 4 + lh, vc1 = vc0 + 2;
        uint32_t v0 = vrow * 256 + ((vc0 ^ (vrow & 7)) << 4);
        uint32_t v1 = vrow * 256 + ((vc1 ^ (vrow & 7)) << 4);
        uint32_t vH0[4], vH1[4], vL0[4], vL1[4];
        ldm4t(vH0, sb + KBH(buf) + v0);
        ldm4t(vH1, sb + KBH(buf) + v1);
        ldm4t(vL0, sb + KBL(buf) + v0);
        ldm4t(vL1, sb + KBL(buf) + v1);
        // hh
        mma16816(oacc + 0,  aH0, vH0[0], vH0[1]);
        mma16816(oacc + 4,  aH0, vH0[2], vH0[3]);
        mma16816(oacc + 8,  aH0, vH1[0], vH1[1]);
        mma16816(oacc + 12, aH0, vH1[2], vH1[3]);
        mma16816(oacc + 16, aH1, vH0[0], vH0[1]);
        mma16816(oacc + 20, aH1, vH0[2], vH0[3]);
        mma16816(oacc + 24, aH1, vH1[0], vH1[1]);
        mma16816(oacc + 28, aH1, vH1[2], vH1[3]);
        // hl
        mma16816(oacc + 0,  aH0, vL0[0], vL0[1]);
        mma16816(oacc + 4,  aH0, vL0[2], vL0[3]);
        mma16816(oacc + 8,  aH0, vL1[0], vL1[1]);
        mma16816(oacc + 12, aH0, vL1[2], vL1[3]);
        mma16816(oacc + 16, aH1, vL0[0], vL0[1]);
        mma16816(oacc + 20, aH1, vL0[2], vL0[3]);
        mma16816(oacc + 24, aH1, vL1[0], vL1[1]);
        mma16816(oacc + 28, aH1, vL1[2], vL1[3]);
        // lh
        mma16816(oacc + 0,  aL0, vH0[0], vH0[1]);
        mma16816(oacc + 4,  aL0, vH0[2], vH0[3]);
        mma16816(oacc + 8,  aL0, vH1[0], vH1[1]);
        mma16816(oacc + 12, aL0, vH1[2], vH1[3]);
        mma16816(oacc + 16, aL1, vH0[0], vH0[1]);
        mma16816(oacc + 20, aL1, vH0[2], vH0[3]);
        mma16816(oacc + 24, aL1, vH1[0], vH1[1]);
        mma16816(oacc + 28, aL1, vH1[2], vH1[3]);
    }
}

__global__ void __launch_bounds__(256, 2)
sparse_attn_ws(const float* __restrict__ q, const float* __restrict__ kv,
               const float* __restrict__ sink, const int* __restrict__ topk,
               float* __restrict__ out) {
    extern __shared__ __align__(1024) unsigned char smem[];
    const uint32_t sb = smem_u32(smem);
    const int tid = threadIdx.x, wid = tid >> 5, lid = tid & 31;
    const int l15 = lid & 15, lh = lid >> 4;
    const int pt = tid & 127;
    const int cw = wid & 3;
    const bool cons = wid < 4;
    const int sq = blockIdx.x;
    float* redm = (float*)(smem + REDM);
    float* reds = (float*)(smem + REDS);
    float* invv = (float*)(smem + INVV);

    float sc[64];
    float oacc[32];

    // ---- s0: consumers convert Q (scaled, split); producers convert K half0 ----
    if (cons) {
        const float* qg = q + (long)sq * 4096;
#pragma unroll
        for (int it = 0; it < 4; it++) {
            int f = pt + it * 128;
            int r = f >> 4, ch = f & 15;
            float v[8];
            *(float4*)(v) = *(const float4*)(qg + r * 128 + ch * 8);
            *(float4*)(v + 4) = *(const float4*)(qg + r * 128 + ch * 8 + 4);
#pragma unroll
            for (int i = 0; i < 8; i++) v[i] *= SCALE_F;
            uint4 H, L; cv8(v, H, L);
            uint32_t o = r * 256 + ((ch ^ (r & 7)) << 4);
            *(uint4*)(smem + QT_H + o) = H;
            *(uint4*)(smem + QT_L + o) = L;
        }
#pragma unroll
        for (int t = 0; t < 64; t++) sc[t] = 0.f;
    } else {
        prod_half(smem, kv, topk, sq, 0, 0, 0, pt);
    }
    __syncthreads();

    // ---- s1-s4: Phase A MMA pipeline ----
    if (cons) mma_A(sb, 0, sc + 0, cw, l15, lh);
    else      prod_half(smem, kv, topk, sq, 0, 1, 1, pt);
    __syncthreads();
    if (cons) mma_A(sb, 1, sc + 16, cw, l15, lh);
    else      prod_half(smem, kv, topk, sq, 0, 2, 0, pt);
    __syncthreads();
    if (cons) mma_A(sb, 0, sc + 32, cw, l15, lh);
    else      prod_half(smem, kv, topk, sq, 0, 3, 1, pt);
    __syncthreads();
    if (cons) mma_A(sb, 1, sc + 48, cw, l15, lh);
    else      prod_half(smem, kv, topk, sq, 128, 0, 0, pt);   // V half0 -> b0
    __syncthreads();

    // ---- s5: consumers softmax (reg scores -> P tiles); producers V half1 ----
    if (cons) {
        // per-thread max over owned rows, per h column
        float mx[8];
#pragma unroll
        for (int jj = 0; jj < 8; jj++) mx[jj] = -1e30f;
#pragma unroll
        for (int hc = 0; hc < 4; hc++)
#pragma unroll
            for (int j = 0; j < 4; j++) {
                float* f = sc + hc * 16 + j * 4;
                mx[j * 2 + 0] = fmaxf(mx[j * 2 + 0], fmaxf(f[0], f[2]));
                mx[j * 2 + 1] = fmaxf(mx[j * 2 + 1], fmaxf(f[1], f[3]));
            }
#pragma unroll
        for (int off = 4; off < 32; off <<= 1)
#pragma unroll
            for (int jj = 0; jj < 8; jj++)
                mx[jj] = fmaxf(mx[jj], __shfl_xor_sync(0xffffffffu, mx[jj], off));
        if (lid < 4) {
#pragma unroll
            for (int jj = 0; jj < 8; jj++)
                redm[cw * 32 + 8 * (jj >> 1) + 2 * lid + (jj & 1)] = mx[jj];
        }
        asm volatile("bar.sync 1, 128;" ::: "memory");
        float mfin[8];
#pragma unroll
        for (int jj = 0; jj < 8; jj++) {
            int h = 8 * (jj >> 1) + 2 * (lid & 3) + (jj & 1);
            float m = __ldg(sink + h);
#pragma unroll
            for (int w = 0; w < 4; w++) m = fmaxf(m, redm[w * 32 + h]);
            mfin[jj] = m;
        }
        float sm[8];
#pragma unroll
        for (int jj = 0; jj < 8; jj++) sm[jj] = 0.f;
#pragma unroll
        for (int hc = 0; hc < 4; hc++)
#pragma unroll
            for (int j = 0; j < 4; j++) {
                int kb = hc * 64 + cw * 16 + (lid >> 2);
                int h0 = 8 * j + 2 * (lid & 3);
                float e0 = __expf(sc[hc * 16 + j * 4 + 0] - mfin[j * 2 + 0]);
                float e1 = __expf(sc[hc * 16 + j * 4 + 1] - mfin[j * 2 + 1]);
                float e2 = __expf(sc[hc * 16 + j * 4 + 2] - mfin[j * 2 + 0]);
                float e3 = __expf(sc[hc * 16 + j * 4 + 3] - mfin[j * 2 + 1]);
                sm[j * 2 + 0] += e0 + e2;
                sm[j * 2 + 1] += e1 + e3;
                unsigned short ph, pl;
                uint32_t o;
                sp(e0, ph, pl);
                o = h0 * 512 + (((kb >> 3) ^ (h0 & 7)) << 4) + ((kb & 7) << 1);
                *(unsigned short*)(smem + P_HI + o) = ph;
                *(unsigned short*)(smem + P_LO + o) = pl;
                sp(e1, ph, pl);
                o = (h0 + 1) * 512 + (((kb >> 3) ^ ((h0 + 1) & 7)) << 4) + ((kb & 7) << 1);
                *(unsigned short*)(smem + P_HI + o) = ph;
                *(unsigned short*)(smem + P_LO + o) = pl;
                int k2 = kb + 8;
                sp(e2, ph, pl);
                o = h0 * 512 + (((k2 >> 3) ^ (h0 & 7)) << 4) + ((k2 & 7) << 1);
                *(unsigned short*)(smem + P_HI + o) = ph;
                *(unsigned short*)(smem + P_LO + o) = pl;
                sp(e3, ph, pl);
                o = (h0 + 1) * 512 + (((k2 >> 3) ^ ((h0 + 1) & 7)) << 4) + ((k2 & 7) << 1);
                *(unsigned short*)(smem + P_HI + o) = ph;
                *(unsigned short*)(smem + P_LO + o) = pl;
            }
#pragma unroll
        for (int off = 4; off < 32; off <<= 1)
#pragma unroll
            for (int jj = 0; jj < 8; jj++)
                sm[jj] += __shfl_xor_sync(0xffffffffu, sm[jj], off);
        if (lid < 4) {
#pragma unroll
            for (int jj = 0; jj < 8; jj++)
                reds[cw * 32 + 8 * (jj >> 1) + 2 * lid + (jj & 1)] = sm[jj];
        }
        asm volatile("bar.sync 1, 128;" ::: "memory");
        if (cw == 0) {
            int h = lid;
            float sk = __ldg(sink + h);
            float m = sk;
#pragma unroll
            for (int w = 0; w < 4; w++) m = fmaxf(m, redm[w * 32 + h]);
            float den = __expf(sk - m);
#pragma unroll
            for (int w = 0; w < 4; w++) den += reds[w * 32 + h];
            invv[h] = 1.f / den;
        }
#pragma unroll
        for (int t = 0; t < 32; t++) oacc[t] = 0.f;
    } else {
        prod_half(smem, kv, topk, sq, 128, 1, 1, pt);   // V half1 -> b1
    }
    __syncthreads();

    // ---- s6-s9: Phase C MMA pipeline ----
    if (cons) mma_C(sb, 0, 0, oacc, cw, l15, lh);
    __syncthreads();
    if (cons) mma_C(sb, 1, 1, oacc, cw, l15, lh);
    else      prod_half(smem, kv, topk, sq, 128, 2, 0, pt);   // V half2 -> b0
    __syncthreads();
    if (cons) mma_C(sb, 0, 2, oacc, cw, l15, lh);
    else      prod_half(smem, kv, topk, sq, 128, 3, 1, pt);   // V half3 -> b1
    __syncthreads();
    if (cons) {
        mma_C(sb, 1, 3, oacc, cw, l15, lh);
        // ---- epilogue: normalize + store ----
        float* op = out + (long)sq * 4096;
#pragma unroll
        for (int i = 0; i < 2; i++) {
            int h0 = 16 * i + (lid >> 2);
            float iv0 = invv[h0], iv1 = invv[h0 + 8];
#pragma unroll
            for (int j = 0; j < 4; j++) {
                int d = cw * 32 + 8 * j + 2 * (lid & 3);
                float* b = oacc + i * 16 + j * 4;
                *(float2*)(op + h0 * 128 + d) = make_float2(b[0] * iv0, b[1] * iv0);
                *(float2*)(op + (h0 + 8) * 128 + d) = make_float2(b[2] * iv1, b[3] * iv1);
            }
        }
    }
}

extern "C" void kernel_launch(void* const* d_in, const int* in_sizes, int n_in,
                              void* d_out, int out_size) {
    (void)in_sizes; (void)n_in; (void)out_size;
    const float* q    = (const float*)d_in[0];
    const float* kv   = (const float*)d_in[1];
    const float* sink = (const float*)d_in[2];
    const int*   topk = (const int*)d_in[3];
    float* out = (float*)d_out;

    cudaFuncSetAttribute(sparse_attn_ws,
                         cudaFuncAttributeMaxDynamicSharedMemorySize, SMEM_BYTES);
    sparse_attn_ws<<<2048, 256, SMEM_BYTES>>>(q, kv, sink, topk, out);
}

// round 6
// speedup vs baseline: 2.4511x; 1.1470x over previous
#include <cuda_runtime.h>
#include <cstdint>

#define SCALE_F 0.08838834764831845f

// ---------------- smem byte offsets ----------------
#define KBH(b) ((b) * 32768)
#define KBL(b) ((b) * 32768 + 16384)
#define QT_H   65536     // Q hi: 32 rows x 256B
#define QT_L   73728     // Q lo
#define P_LO   65536     // P lo aliases QT (Q dead by softmax)
#define P_HI   81920     // P hi: 32 h x 512B
#define REDM   98304
#define REDS   98816
#define INVV   99328
#define SIDX   99456     // 256 int32 cached indices
#define SMEM_BYTES 100480

// ---------------- helpers ----------------
static __device__ __forceinline__ uint32_t smem_u32(const void* p) {
    uint32_t a;
    asm("{ .reg .u64 t; cvta.to.shared.u64 t, %1; cvt.u32.u64 %0, t; }" : "=r"(a) : "l"(p));
    return a;
}
static __device__ __forceinline__ void ldm4(uint32_t* r, uint32_t addr) {
    asm volatile("ldmatrix.sync.aligned.m8n8.x4.shared.b16 {%0,%1,%2,%3}, [%4];"
                 : "=r"(r[0]), "=r"(r[1]), "=r"(r[2]), "=r"(r[3]) : "r"(addr));
}
static __device__ __forceinline__ void ldm4t(uint32_t* r, uint32_t addr) {
    asm volatile("ldmatrix.sync.aligned.m8n8.x4.trans.shared.b16 {%0,%1,%2,%3}, [%4];"
                 : "=r"(r[0]), "=r"(r[1]), "=r"(r[2]), "=r"(r[3]) : "r"(addr));
}
static __device__ __forceinline__ void mma16816(float* c, const uint32_t* a,
                                                uint32_t b0, uint32_t b1) {
    asm volatile("mma.sync.aligned.m16n8k16.row.col.f32.bf16.bf16.f32 "
                 "{%0,%1,%2,%3}, {%4,%5,%6,%7}, {%8,%9}, {%0,%1,%2,%3};"
                 : "+f"(c[0]), "+f"(c[1]), "+f"(c[2]), "+f"(c[3])
                 : "r"(a[0]), "r"(a[1]), "r"(a[2]), "r"(a[3]), "r"(b0), "r"(b1));
}
// scalar split (softmax path): hi = truncate-to-bf16 (exact residual), lo = rn(resid)
static __device__ __forceinline__ void sp(float x, unsigned short& h, unsigned short& l) {
    unsigned xb = __float_as_uint(x);
    h = (unsigned short)(xb >> 16);
    float r = x - __uint_as_float(xb & 0xFFFF0000u);
    asm("cvt.rn.bf16.f32 %0, %1;" : "=h"(l) : "f"(r));
}
// 8-float split via PRMT (hi pairs) + cvt.bf16x2 (lo pairs): ~24 instr
static __device__ __forceinline__ void cv8t(const float* f, uint4& H, uint4& L) {
    const unsigned* u = (const unsigned*)f;
    unsigned* hp = (unsigned*)&H;
    unsigned* lp = (unsigned*)&L;
#pragma unroll
    for (int i = 0; i < 4; i++) {
        unsigned x0 = u[2 * i], x1 = u[2 * i + 1];
        asm("prmt.b32 %0, %1, %2, 0x7632;" : "=r"(hp[i]) : "r"(x0), "r"(x1));
        float r0 = __uint_as_float(x0) - __uint_as_float(x0 & 0xFFFF0000u);
        float r1 = __uint_as_float(x1) - __uint_as_float(x1 & 0xFFFF0000u);
        asm("cvt.rn.bf16x2.f32 %0, %1, %2;" : "=r"(lp[i]) : "f"(r1), "f"(r0));
    }
}

// producer: gather + split-convert one 64-row half into buffer buf
static __device__ __forceinline__ void prod_half(
    unsigned char* smem, const float* kv, const int* sidx,
    int base, int hc, int buf, int pt) {
    const int ch = pt & 15;
    const int r0 = pt >> 4;
#pragma unroll
    for (int bb = 0; bb < 4; bb++) {
        float v[2][8];
        int r[2];
#pragma unroll
        for (int it = 0; it < 2; it++) {
            r[it] = r0 + (bb * 2 + it) * 8;
            int id = sidx[hc * 64 + r[it]];
            const float* src = kv + (long)id * 256 + base + ch * 8;
            *(float4*)(v[it]) = *(const float4*)(src);
            *(float4*)(v[it] + 4) = *(const float4*)(src + 4);
        }
#pragma unroll
        for (int it = 0; it < 2; it++) {
            uint4 H, L; cv8t(v[it], H, L);
            uint32_t o = r[it] * 256 + ((ch ^ (r[it] & 7)) << 4);
            *(uint4*)(smem + KBH(buf) + o) = H;
            *(uint4*)(smem + KBL(buf) + o) = L;
        }
    }
}

// consumer Phase A: 64-row half-chunk, warp tile M16 x N32, 3-term split
static __device__ __forceinline__ void mma_A(
    uint32_t sb, int buf, float* scc, int cw, int l15, int lh) {
    const int arow = cw * 16 + l15;
    const int qrow0 = l15, qrow1 = 16 + l15;
#pragma unroll
    for (int s = 0; s < 8; s++) {
        int ch = 2 * s + lh;
        uint32_t ao = arow * 256 + ((ch ^ (arow & 7)) << 4);
        uint32_t q0 = qrow0 * 256 + ((ch ^ (qrow0 & 7)) << 4);
        uint32_t q1 = qrow1 * 256 + ((ch ^ (qrow1 & 7)) << 4);
        uint32_t aH[4], aL[4], bH0[4], bH1[4], bL0[4], bL1[4];
        ldm4(aH, sb + KBH(buf) + ao);
        ldm4(aL, sb + KBL(buf) + ao);
        ldm4(bH0, sb + QT_H + q0);
        ldm4(bH1, sb + QT_H + q1);
        ldm4(bL0, sb + QT_L + q0);
        ldm4(bL1, sb + QT_L + q1);
        mma16816(scc + 0,  aH, bH0[0], bH0[2]);
        mma16816(scc + 4,  aH, bH0[1], bH0[3]);
        mma16816(scc + 8,  aH, bH1[0], bH1[2]);
        mma16816(scc + 12, aH, bH1[1], bH1[3]);
        mma16816(scc + 0,  aH, bL0[0], bL0[2]);
        mma16816(scc + 4,  aH, bL0[1], bL0[3]);
        mma16816(scc + 8,  aH, bL1[0], bL1[2]);
        mma16816(scc + 12, aH, bL1[1], bL1[3]);
        mma16816(scc + 0,  aL, bH0[0], bH0[2]);
        mma16816(scc + 4,  aL, bH0[1], bH0[3]);
        mma16816(scc + 8,  aL, bH1[0], bH1[2]);
        mma16816(scc + 12, aL, bH1[1], bH1[3]);
    }
}

// consumer Phase C: 64 V-rows in buf (global k half hcl), warp tile M32h x N32d
static __device__ __forceinline__ void mma_C(
    uint32_t sb, int buf, int hcl, float* oacc, int cw, int l15, int lh) {
#pragma unroll
    for (int s = 0; s < 4; s++) {
        int pch = hcl * 8 + 2 * s + lh;
        uint32_t po0 = l15 * 512 + ((pch ^ (l15 & 7)) << 4);
        uint32_t po1 = po0 + 8192;
        uint32_t aH0[4], aH1[4], aL0[4], aL1[4];
        ldm4(aH0, sb + P_HI + po0);
        ldm4(aH1, sb + P_HI + po1);
        ldm4(aL0, sb + P_LO + po0);
        ldm4(aL1, sb + P_LO + po1);
        int vrow = s * 16 + l15;
        uint32_t vc0 = cw * 4 + lh, vc1 = vc0 + 2;
        uint32_t v0 = vrow * 256 + ((vc0 ^ (vrow & 7)) << 4);
        uint32_t v1 = vrow * 256 + ((vc1 ^ (vrow & 7)) << 4);
        uint32_t vH0[4], vH1[4], vL0[4], vL1[4];
        ldm4t(vH0, sb + KBH(buf) + v0);
        ldm4t(vH1, sb + KBH(buf) + v1);
        ldm4t(vL0, sb + KBL(buf) + v0);
        ldm4t(vL1, sb + KBL(buf) + v1);
        mma16816(oacc + 0,  aH0, vH0[0], vH0[1]);
        mma16816(oacc + 4,  aH0, vH0[2], vH0[3]);
        mma16816(oacc + 8,  aH0, vH1[0], vH1[1]);
        mma16816(oacc + 12, aH0, vH1[2], vH1[3]);
        mma16816(oacc + 16, aH1, vH0[0], vH0[1]);
        mma16816(oacc + 20, aH1, vH0[2], vH0[3]);
        mma16816(oacc + 24, aH1, vH1[0], vH1[1]);
        mma16816(oacc + 28, aH1, vH1[2], vH1[3]);
        mma16816(oacc + 0,  aH0, vL0[0], vL0[1]);
        mma16816(oacc + 4,  aH0, vL0[2], vL0[3]);
        mma16816(oacc + 8,  aH0, vL1[0], vL1[1]);
        mma16816(oacc + 12, aH0, vL1[2], vL1[3]);
        mma16816(oacc + 16, aH1, vL0[0], vL0[1]);
        mma16816(oacc + 20, aH1, vL0[2], vL0[3]);
        mma16816(oacc + 24, aH1, vL1[0], vL1[1]);
        mma16816(oacc + 28, aH1, vL1[2], vL1[3]);
        mma16816(oacc + 0,  aL0, vH0[0], vH0[1]);
        mma16816(oacc + 4,  aL0, vH0[2], vH0[3]);
        mma16816(oacc + 8,  aL0, vH1[0], vH1[1]);
        mma16816(oacc + 12, aL0, vH1[2], vH1[3]);
        mma16816(oacc + 16, aL1, vH0[0], vH0[1]);
        mma16816(oacc + 20, aL1, vH0[2], vH0[3]);
        mma16816(oacc + 24, aL1, vH1[0], vH1[1]);
        mma16816(oacc + 28, aL1, vH1[2], vH1[3]);
    }
}

__global__ void __launch_bounds__(256, 2)
sparse_attn_ws(const float* __restrict__ q, const float* __restrict__ kv,
               const float* __restrict__ sink, const int* __restrict__ topk,
               float* __restrict__ out) {
    extern __shared__ __align__(1024) unsigned char smem[];
    const uint32_t sb = smem_u32(smem);
    const int tid = threadIdx.x, wid = tid >> 5, lid = tid & 31;
    const int l15 = lid & 15, lh = lid >> 4;
    const int pt = tid & 127;
    const int cw = wid & 3;
    const bool cons = wid < 4;
    const int sq = blockIdx.x;
    float* redm = (float*)(smem + REDM);
    float* reds = (float*)(smem + REDS);
    float* invv = (float*)(smem + INVV);
    int*   sidx = (int*)(smem + SIDX);

    float sc[64];
    float oacc[32];

    // ---- s0: consumers convert Q; producers cache indices + K half0 ----
    if (cons) {
        const float* qg = q + (long)sq * 4096;
#pragma unroll
        for (int it = 0; it < 4; it++) {
            int f = pt + it * 128;
            int r = f >> 4, ch = f & 15;
            float v[8];
            *(float4*)(v) = *(const float4*)(qg + r * 128 + ch * 8);
            *(float4*)(v + 4) = *(const float4*)(qg + r * 128 + ch * 8 + 4);
#pragma unroll
            for (int i = 0; i < 8; i++) v[i] *= SCALE_F;
            uint4 H, L; cv8t(v, H, L);
            uint32_t o = r * 256 + ((ch ^ (r & 7)) << 4);
            *(uint4*)(smem + QT_H + o) = H;
            *(uint4*)(smem + QT_L + o) = L;
        }
#pragma unroll
        for (int t = 0; t < 64; t++) sc[t] = 0.f;
    } else {
        sidx[pt]       = __ldg(topk + (long)sq * 256 + pt);
        sidx[pt + 128] = __ldg(topk + (long)sq * 256 + 128 + pt);
        asm volatile("bar.sync 2, 128;" ::: "memory");
        prod_half(smem, kv, sidx, 0, 0, 0, pt);
    }
    __syncthreads();

    // ---- s1-s4: Phase A MMA pipeline ----
    if (cons) mma_A(sb, 0, sc + 0, cw, l15, lh);
    else      prod_half(smem, kv, sidx, 0, 1, 1, pt);
    __syncthreads();
    if (cons) mma_A(sb, 1, sc + 16, cw, l15, lh);
    else      prod_half(smem, kv, sidx, 0, 2, 0, pt);
    __syncthreads();
    if (cons) mma_A(sb, 0, sc + 32, cw, l15, lh);
    else      prod_half(smem, kv, sidx, 0, 3, 1, pt);
    __syncthreads();
    if (cons) mma_A(sb, 1, sc + 48, cw, l15, lh);
    else      prod_half(smem, kv, sidx, 128, 0, 0, pt);   // V half0 -> b0
    __syncthreads();

    // ---- s5: consumers softmax; producers V half1 ----
    if (cons) {
        float mx[8];
#pragma unroll
        for (int jj = 0; jj < 8; jj++) mx[jj] = -1e30f;
#pragma unroll
        for (int hc = 0; hc < 4; hc++)
#pragma unroll
            for (int j = 0; j < 4; j++) {
                float* f = sc + hc * 16 + j * 4;
                mx[j * 2 + 0] = fmaxf(mx[j * 2 + 0], fmaxf(f[0], f[2]));
                mx[j * 2 + 1] = fmaxf(mx[j * 2 + 1], fmaxf(f[1], f[3]));
            }
#pragma unroll
        for (int off = 4; off < 32; off <<= 1)
#pragma unroll
            for (int jj = 0; jj < 8; jj++)
                mx[jj] = fmaxf(mx[jj], __shfl_xor_sync(0xffffffffu, mx[jj], off));
        if (lid < 4) {
#pragma unroll
            for (int jj = 0; jj < 8; jj++)
                redm[cw * 32 + 8 * (jj >> 1) + 2 * lid + (jj & 1)] = mx[jj];
        }
        asm volatile("bar.sync 1, 128;" ::: "memory");
        float mfin[8];
#pragma unroll
        for (int jj = 0; jj < 8; jj++) {
            int h = 8 * (jj >> 1) + 2 * (lid & 3) + (jj & 1);
            float m = __ldg(sink + h);
#pragma unroll
            for (int w = 0; w < 4; w++) m = fmaxf(m, redm[w * 32 + h]);
            mfin[jj] = m;
        }
        float sm[8];
#pragma unroll
        for (int jj = 0; jj < 8; jj++) sm[jj] = 0.f;
#pragma unroll
        for (int hc = 0; hc < 4; hc++)
#pragma unroll
            for (int j = 0; j < 4; j++) {
                int kb = hc * 64 + cw * 16 + (lid >> 2);
                int h0 = 8 * j + 2 * (lid & 3);
                float e0 = __expf(sc[hc * 16 + j * 4 + 0] - mfin[j * 2 + 0]);
                float e1 = __expf(sc[hc * 16 + j * 4 + 1] - mfin[j * 2 + 1]);
                float e2 = __expf(sc[hc * 16 + j * 4 + 2] - mfin[j * 2 + 0]);
                float e3 = __expf(sc[hc * 16 + j * 4 + 3] - mfin[j * 2 + 1]);
                sm[j * 2 + 0] += e0 + e2;
                sm[j * 2 + 1] += e1 + e3;
                unsigned short ph, pl;
                uint32_t o;
                sp(e0, ph, pl);
                o = h0 * 512 + (((kb >> 3) ^ (h0 & 7)) << 4) + ((kb & 7) << 1);
                *(unsigned short*)(smem + P_HI + o) = ph;
                *(unsigned short*)(smem + P_LO + o) = pl;
                sp(e1, ph, pl);
                o = (h0 + 1) * 512 + (((kb >> 3) ^ ((h0 + 1) & 7)) << 4) + ((kb & 7) << 1);
                *(unsigned short*)(smem + P_HI + o) = ph;
                *(unsigned short*)(smem + P_LO + o) = pl;
                int k2 = kb + 8;
                sp(e2, ph, pl);
                o = h0 * 512 + (((k2 >> 3) ^ (h0 & 7)) << 4) + ((k2 & 7) << 1);
                *(unsigned short*)(smem + P_HI + o) = ph;
                *(unsigned short*)(smem + P_LO + o) = pl;
                sp(e3, ph, pl);
                o = (h0 + 1) * 512 + (((k2 >> 3) ^ ((h0 + 1) & 7)) << 4) + ((k2 & 7) << 1);
                *(unsigned short*)(smem + P_HI + o) = ph;
                *(unsigned short*)(smem + P_LO + o) = pl;
            }
#pragma unroll
        for (int off = 4; off < 32; off <<= 1)
#pragma unroll
            for (int jj = 0; jj < 8; jj++)
                sm[jj] += __shfl_xor_sync(0xffffffffu, sm[jj], off);
        if (lid < 4) {
#pragma unroll
            for (int jj = 0; jj < 8; jj++)
                reds[cw * 32 + 8 * (jj >> 1) + 2 * lid + (jj & 1)] = sm[jj];
        }
        asm volatile("bar.sync 1, 128;" ::: "memory");
        if (cw == 0) {
            int h = lid;
            float sk = __ldg(sink + h);
            float m = sk;
#pragma unroll
            for (int w = 0; w < 4; w++) m = fmaxf(m, redm[w * 32 + h]);
            float den = __expf(sk - m);
#pragma unroll
            for (int w = 0; w < 4; w++) den += reds[w * 32 + h];
            invv[h] = 1.f / den;
        }
#pragma unroll
        for (int t = 0; t < 32; t++) oacc[t] = 0.f;
    } else {
        prod_half(smem, kv, sidx, 128, 1, 1, pt);   // V half1 -> b1
    }
    __syncthreads();

    // ---- s6-s9: Phase C MMA pipeline ----
    if (cons) mma_C(sb, 0, 0, oacc, cw, l15, lh);
    __syncthreads();
    if (cons) mma_C(sb, 1, 1, oacc, cw, l15, lh);
    else      prod_half(smem, kv, sidx, 128, 2, 0, pt);   // V half2 -> b0
    __syncthreads();
    if (cons) mma_C(sb, 0, 2, oacc, cw, l15, lh);
    else      prod_half(smem, kv, sidx, 128, 3, 1, pt);   // V half3 -> b1
    __syncthreads();
    if (cons) {
        mma_C(sb, 1, 3, oacc, cw, l15, lh);
        float* op = out + (long)sq * 4096;
#pragma unroll
        for (int i = 0; i < 2; i++) {
            int h0 = 16 * i + (lid >> 2);
            float iv0 = invv[h0], iv1 = invv[h0 + 8];
#pragma unroll
            for (int j = 0; j < 4; j++) {
                int d = cw * 32 + 8 * j + 2 * (lid & 3);
                float* b = oacc + i * 16 + j * 4;
                *(float2*)(op + h0 * 128 + d) = make_float2(b[0] * iv0, b[1] * iv0);
                *(float2*)(op + (h0 + 8) * 128 + d) = make_float2(b[2] * iv1, b[3] * iv1);
            }
        }
    }
}

extern "C" void kernel_launch(void* const* d_in, const int* in_sizes, int n_in,
                              void* d_out, int out_size) {
    (void)in_sizes; (void)n_in; (void)out_size;
    const float* q    = (const float*)d_in[0];
    const float* kv   = (const float*)d_in[1];
    const float* sink = (const float*)d_in[2];
    const int*   topk = (const int*)d_in[3];
    float* out = (float*)d_out;

    cudaFuncSetAttribute(sparse_attn_ws,
                         cudaFuncAttributeMaxDynamicSharedMemorySize, SMEM_BYTES);
    sparse_attn_ws<<<2048, 256, SMEM_BYTES>>>(q, kv, sink, topk, out);
}